// round 17
// baseline (speedup 1.0000x reference)
#include <cuda_runtime.h>
#include <cuda_fp16.h>
#include <math.h>
#include <stdint.h>

#define BATCH_N 32768
#define IN_DIM  1024
#define ATTN_D  128
#define OUT_D   1024
#define NHEADS  8

#define KT      128
#define PADE    136                /* fp16 elems per smem row (128 data + 8 pad) */
#define ROWB    (PADE * 2)         /* 272 bytes per row */
#define TILE_B  (128 * ROWB)       /* 34816 bytes */
#define NSTAGE  3
#define BUFB    (2 * TILE_B)       /* A + B = 69632 */
#define AOFF    (NSTAGE * BUFB)    /* 208896: attnS / sdot */
#define SMEM_SZ (AOFF + 4096)      /* 212992 */

// ---------------- device-global scratch (no cudaMalloc allowed) --------
__device__ float g_q[(size_t)BATCH_N * ATTN_D];
__device__ float g_dot[BATCH_N * NHEADS];
__device__ float g_attn[BATCH_N * NHEADS];
__device__ uint2 g_x16[(size_t)BATCH_N * IN_DIM / 4];
__device__ uint2 g_wq16[ATTN_D * IN_DIM / 4];
__device__ uint2 g_wk16[NHEADS * ATTN_D * IN_DIM / 4];
__device__ uint2 g_wv16[(size_t)NHEADS * OUT_D * IN_DIM / 4];

__device__ __forceinline__ unsigned smem_u32(const void* p) {
    return (unsigned)__cvta_generic_to_shared(p);
}

__global__ void conv_f16_kernel(const float4* __restrict__ src, uint2* __restrict__ dst, int n4) {
    int i = blockIdx.x * blockDim.x + threadIdx.x;
    if (i < n4) {
        float4 v = src[i];
        __half2 h01 = __floats2half2_rn(v.x, v.y);
        __half2 h23 = __floats2half2_rn(v.z, v.w);
        uint2 h; h.x = *(unsigned*)&h01; h.y = *(unsigned*)&h23;
        dst[i] = h;
    }
}

__device__ __forceinline__ void ldsm_x4(unsigned* r, unsigned addr) {
    asm volatile("ldmatrix.sync.aligned.m8n8.x4.shared.b16 {%0,%1,%2,%3}, [%4];"
                 : "=r"(r[0]), "=r"(r[1]), "=r"(r[2]), "=r"(r[3]) : "r"(addr));
}
__device__ __forceinline__ void mma_f16(float* d, const unsigned* a, const unsigned* b) {
    asm volatile(
        "mma.sync.aligned.m16n8k16.row.col.f32.f16.f16.f32 "
        "{%0,%1,%2,%3}, {%4,%5,%6,%7}, {%8,%9}, {%0,%1,%2,%3};"
        : "+f"(d[0]), "+f"(d[1]), "+f"(d[2]), "+f"(d[3])
        : "r"(a[0]), "r"(a[1]), "r"(a[2]), "r"(a[3]), "r"(b[0]), "r"(b[1]));
}

#define CP16(sm, gp) asm volatile("cp.async.cg.shared.global [%0], [%1], 16;" \
                                  :: "r"(sm), "l"(gp) : "memory")
#define CP_COMMIT()  asm volatile("cp.async.commit_group;" ::: "memory")
#define CP_WAIT1()   asm volatile("cp.async.wait_group 1;" ::: "memory")

// MODE 0: Q gemm (N=128)             out=g_q     (NKT=8)
// MODE 1: K gemm + q.k dot epilogue  out=g_dot, aux=g_q   (NKT=8)
// MODE 2: V gemm, per-head reg merge out=d_out, aux=g_attn (NKT=64)
template <int MODE, int NKT>
__global__ void __launch_bounds__(256, 1)
gemm_kernel(const char* __restrict__ A16, const char* __restrict__ B16,
            const float* __restrict__ bias, const float* __restrict__ aux,
            float* __restrict__ out) {
    extern __shared__ char smem[];
    const unsigned sbase = smem_u32(smem);
    const int tid  = threadIdx.x;
    const int warp = tid >> 5, lane = tid & 31;
    const int bm = blockIdx.x;
    const int bn = blockIdx.y;
    const int rowBase = bm * 128;
    const int bRowBase = (MODE == 0) ? 0 : bn * 128;

    float* attnS = (float*)(smem + AOFF);
    float* sdot  = (float*)(smem + AOFF);

    if (MODE == 1) { if (tid < 128) sdot[tid] = 0.f; }
    if (MODE == 2) {
        for (int i = tid; i < 128 * NHEADS; i += 256)
            attnS[i] = aux[(size_t)(rowBase + (i >> 3)) * NHEADS + (i & 7)];
    }

    // per-thread copy slots: rows r0+16i (i=0..7), 16B chunk c of 256B row data
    const int r0 = tid >> 4;            // 0..15
    const int c  = tid & 15;            // 0..15
    const size_t aOff0 = ((size_t)(rowBase + r0) * IN_DIM + c * 8) * 2;
    const size_t bOff0 = ((size_t)(bRowBase + r0) * IN_DIM + c * 8) * 2;
    const unsigned smA0 = r0 * ROWB + c * 16;
    const size_t gStride = (size_t)16 * IN_DIM * 2;   // 16 rows in gmem
    const unsigned sStride = 16 * ROWB;               // 16 rows in smem

    auto LOAD = [&](int s, int bi) {
        if (s < NKT) {
            const unsigned sb = sbase + bi * BUFB;
            const size_t ka = (size_t)((s * KT) & (IN_DIM - 1)) * 2;
            const size_t kb = (MODE == 2)
                ? ka + (size_t)(s >> 3) * ((size_t)OUT_D * IN_DIM * 2) : ka;
#pragma unroll
            for (int i = 0; i < 8; i++) {
                CP16(sb + smA0 + i * sStride,          A16 + aOff0 + ka + i * gStride);
                CP16(sb + TILE_B + smA0 + i * sStride, B16 + bOff0 + kb + i * gStride);
            }
        }
        CP_COMMIT();
    };

    const int wm = (warp >> 2) * 64;
    const int wn = (warp & 3) * 32;
    const unsigned lrow  = lane & 15;
    const unsigned lcolB = (lane >> 4) * 16;

    float acc[4][4][4];
    float accT[4][4][4];
#pragma unroll
    for (int a = 0; a < 4; a++)
#pragma unroll
        for (int b = 0; b < 4; b++)
#pragma unroll
            for (int cc = 0; cc < 4; cc++) { acc[a][b][cc] = 0.f; if (MODE == 2) accT[a][b][cc] = 0.f; }

    auto COMPUTE = [&](int bi) {
        const unsigned base = sbase + bi * BUFB;
#pragma unroll
        for (int ks = 0; ks < 8; ks++) {
            const unsigned kb = ks * 32 + lcolB;
            unsigned af[4][4], bf[2][4];
#pragma unroll
            for (int mf = 0; mf < 4; mf++) {
                unsigned ad = base + (wm + mf * 16 + lrow) * ROWB + kb;
                ldsm_x4(af[mf], ad);
            }
#pragma unroll
            for (int nf2 = 0; nf2 < 2; nf2++) {
                unsigned bd = base + TILE_B + (wn + nf2 * 16 + lrow) * ROWB + kb;
                ldsm_x4(bf[nf2], bd);
            }
#pragma unroll
            for (int mf = 0; mf < 4; mf++)
#pragma unroll
                for (int nf = 0; nf < 4; nf++) {
                    unsigned bh[2] = { bf[nf >> 1][nf & 1], bf[nf >> 1][(nf & 1) + 2] };
                    mma_f16(acc[mf][nf], af[mf], bh);
                }
        }
    };

    LOAD(0, 0); LOAD(1, 1);

    int bi = 0, li = 2;
    for (int s = 0; s < NKT; s++) {
        CP_WAIT1();
        __syncthreads();
        COMPUTE(bi);
        LOAD(s + 2, li);
        if (MODE == 2 && ((s & 7) == 7)) {
            const int h = s >> 3;
#pragma unroll
            for (int mf = 0; mf < 4; mf++)
#pragma unroll
                for (int eh = 0; eh < 2; eh++) {
                    const float sc = attnS[(wm + (lane >> 2) + mf * 16 + eh * 8) * NHEADS + h];
#pragma unroll
                    for (int nf = 0; nf < 4; nf++)
#pragma unroll
                        for (int e = 0; e < 2; e++) {
                            accT[mf][nf][eh * 2 + e] += sc * acc[mf][nf][eh * 2 + e];
                            acc[mf][nf][eh * 2 + e] = 0.f;
                        }
                }
        }
        bi = (bi == 2) ? 0 : bi + 1;
        li = (li == 2) ? 0 : li + 1;
    }

    // ---- epilogue ----
    const int erow0 = wm + (lane >> 2);
    const int ecol0 = wn + (lane & 3) * 2;

    if (MODE == 0) {
#pragma unroll
        for (int mf = 0; mf < 4; mf++)
#pragma unroll
            for (int e2 = 0; e2 < 2; e2++) {
                int r = rowBase + erow0 + mf * 16 + e2 * 8;
#pragma unroll
                for (int nf = 0; nf < 4; nf++) {
                    int cc = ecol0 + nf * 8;
                    float2 v;
                    v.x = acc[mf][nf][e2 * 2 + 0] + bias[cc];
                    v.y = acc[mf][nf][e2 * 2 + 1] + bias[cc + 1];
                    *(float2*)(out + (size_t)r * ATTN_D + cc) = v;
                }
            }
    } else if (MODE == 1) {
#pragma unroll
        for (int mf = 0; mf < 4; mf++)
#pragma unroll
            for (int e2 = 0; e2 < 2; e2++) {
                int rl = erow0 + mf * 16 + e2 * 8;
                int rg = rowBase + rl;
                float s = 0.f;
#pragma unroll
                for (int nf = 0; nf < 4; nf++) {
                    int cc = ecol0 + nf * 8;
                    float q0 = aux[(size_t)rg * ATTN_D + cc];
                    float q1 = aux[(size_t)rg * ATTN_D + cc + 1];
                    s += (acc[mf][nf][e2 * 2 + 0] + bias[bn * ATTN_D + cc])     * q0;
                    s += (acc[mf][nf][e2 * 2 + 1] + bias[bn * ATTN_D + cc + 1]) * q1;
                }
                atomicAdd(&sdot[rl], s);
            }
        __syncthreads();
        if (tid < 128)
            out[(size_t)(rowBase + tid) * NHEADS + bn] = sdot[tid];
    } else {
#pragma unroll
        for (int nf = 0; nf < 4; nf++) {
            int cc = bn * 128 + ecol0 + nf * 8;
            float bv0[NHEADS], bv1[NHEADS];
#pragma unroll
            for (int h = 0; h < NHEADS; h++) {
                bv0[h] = bias[h * OUT_D + cc];
                bv1[h] = bias[h * OUT_D + cc + 1];
            }
#pragma unroll
            for (int mf = 0; mf < 4; mf++)
#pragma unroll
                for (int e2 = 0; e2 < 2; e2++) {
                    int rl = erow0 + mf * 16 + e2 * 8;
                    int rg = rowBase + rl;
                    float b0 = 0.f, b1 = 0.f;
#pragma unroll
                    for (int h = 0; h < NHEADS; h++) {
                        float at = attnS[rl * NHEADS + h];
                        b0 += at * bv0[h];
                        b1 += at * bv1[h];
                    }
                    float2 v;
                    v.x = accT[mf][nf][e2 * 2 + 0] + b0;
                    v.y = accT[mf][nf][e2 * 2 + 1] + b1;
                    *(float2*)(out + (size_t)rg * OUT_D + cc) = v;
                }
        }
    }
}

__global__ void softmax_kernel(const float* __restrict__ dot, float* __restrict__ attn) {
    int b = blockIdx.x * blockDim.x + threadIdx.x;
    if (b >= BATCH_N) return;
    const float sc = 0.08838834764831845f;
    float d[NHEADS], m = -1e30f;
#pragma unroll
    for (int h = 0; h < NHEADS; h++) { d[h] = dot[b * NHEADS + h] * sc; m = fmaxf(m, d[h]); }
    float s = 0.f;
#pragma unroll
    for (int h = 0; h < NHEADS; h++) { d[h] = __expf(d[h] - m); s += d[h]; }
    float inv = 1.f / s;
#pragma unroll
    for (int h = 0; h < NHEADS; h++) attn[b * NHEADS + h] = d[h] * inv;
}

extern "C" void kernel_launch(void* const* d_in, const int* in_sizes, int n_in,
                              void* d_out, int out_size) {
    const float* x  = (const float*)d_in[0];
    const float* Wq = (const float*)d_in[1];
    const float* bq = (const float*)d_in[2];
    const float* Wk = (const float*)d_in[3];
    const float* bk = (const float*)d_in[4];
    const float* Wv = (const float*)d_in[5];
    const float* bv = (const float*)d_in[6];
    float* out = (float*)d_out;

    float *qp, *dp, *ap;
    cudaGetSymbolAddress((void**)&qp, g_q);
    cudaGetSymbolAddress((void**)&dp, g_dot);
    cudaGetSymbolAddress((void**)&ap, g_attn);
    uint2 *x16, *wq16, *wk16, *wv16;
    cudaGetSymbolAddress((void**)&x16,  g_x16);
    cudaGetSymbolAddress((void**)&wq16, g_wq16);
    cudaGetSymbolAddress((void**)&wk16, g_wk16);
    cudaGetSymbolAddress((void**)&wv16, g_wv16);

    cudaFuncSetAttribute(gemm_kernel<0, 8>,  cudaFuncAttributeMaxDynamicSharedMemorySize, SMEM_SZ);
    cudaFuncSetAttribute(gemm_kernel<1, 8>,  cudaFuncAttributeMaxDynamicSharedMemorySize, SMEM_SZ);
    cudaFuncSetAttribute(gemm_kernel<2, 64>, cudaFuncAttributeMaxDynamicSharedMemorySize, SMEM_SZ);

    // pre-pass: fp32 -> fp16 conversions
    {
        int n4;
        n4 = BATCH_N * IN_DIM / 4;
        conv_f16_kernel<<<(n4 + 255) / 256, 256>>>((const float4*)x, x16, n4);
        n4 = ATTN_D * IN_DIM / 4;
        conv_f16_kernel<<<(n4 + 255) / 256, 256>>>((const float4*)Wq, wq16, n4);
        n4 = NHEADS * ATTN_D * IN_DIM / 4;
        conv_f16_kernel<<<(n4 + 255) / 256, 256>>>((const float4*)Wk, wk16, n4);
        n4 = (int)((size_t)NHEADS * OUT_D * IN_DIM / 4);
        conv_f16_kernel<<<(n4 + 255) / 256, 256>>>((const float4*)Wv, wv16, n4);
    }

    gemm_kernel<0, 8><<<dim3(BATCH_N / 128, 1), 256, SMEM_SZ>>>(
        (const char*)x16, (const char*)wq16, bq, nullptr, qp);
    gemm_kernel<1, 8><<<dim3(BATCH_N / 128, NHEADS), 256, SMEM_SZ>>>(
        (const char*)x16, (const char*)wk16, bk, qp, dp);
    softmax_kernel<<<BATCH_N / 256, 256>>>(dp, ap);
    gemm_kernel<2, 64><<<dim3(BATCH_N / 128, NHEADS), 256, SMEM_SZ>>>(
        (const char*)x16, (const char*)wv16, bv, ap, out);
}